// round 16
// baseline (speedup 1.0000x reference)
#include <cuda_runtime.h>

#define THETA 0.9999f
#define MAXN 256

// r3 spike-rate exchange buffer: [n][32][87]
__device__ float g_r3[MAXN * 32 * 87];

// IF-neuron spike rate over 50 steps, constant drive a, soft reset.
// Closed form floor(50*a/theta); exact f32 sim only near count boundaries.
__device__ __forceinline__ float rate50(float a) {
    if (a <= 0.0f) return 0.0f;
    if (a >= THETA) return 1.0f;
    float u = a * (50.0f / THETA);
    float k = floorf(u);
    float d = u - k;
    if (d > 1e-4f && d < 0.9999f) {
        return k * 0.02f;
    }
    float v = 0.0f, cnt = 0.0f;
    #pragma unroll
    for (int t = 0; t < 50; ++t) {
        v += a;
        if (v >= THETA) { v -= THETA; cnt += 1.0f; }
    }
    return cnt * 0.02f;
}

__global__ void zero_out_kernel(float* __restrict__ out, int n) {
    int i = blockIdx.x * blockDim.x + threadIdx.x;
    if (i < n) out[i] = 0.0f;
}

// ===================== K1: mx, r1, half of r2, pool -> g_r3 =====================
// Shared (floats): A mx [0,184) data at h+1; B r1 [184,3128) 16 x stride 184 (h+1);
// C r2local [3128,5944) 16 x stride 176; W2s [5944,8264) 16 rows x stride 145.
#define K1_B   184
#define K1_C   3128
#define K1_W2  5944
#define K1_TOT 8264

__global__ __launch_bounds__(256, 4)
void catnet_k1(const float* __restrict__ x,
               const float* __restrict__ w1, const float* __restrict__ b1,
               const float* __restrict__ w2, const float* __restrict__ b2) {
    __shared__ float sm[K1_TOT];
    float* A   = sm;
    float* B   = sm + K1_B;
    float* C   = sm + K1_C;
    float* W2s = sm + K1_W2;
    const int tid = threadIdx.x;
    const int n = blockIdx.x >> 1;
    const int cg = blockIdx.x & 1;
    const int obase = cg * 16;

    // stage this CTA's 16 w2 output rows (o*16*9 floats each) into smem
    #pragma unroll 2
    for (int i = tid; i < 16 * 144; i += 256) {
        int ol = i / 144;
        int r = i - ol * 144;
        W2s[ol * 145 + r] = w2[(obase + ol) * 144 + r];
    }
    // zero working region (pad cells; finite values under any over-read)
    for (int i = tid; i < K1_W2; i += 256) sm[i] = 0.0f;
    __syncthreads();

    // ---- stage 0: mean over time -> A[h+1] ----
    const float2* xn2 = (const float2*)(x + (long)n * (180 * 50));
    for (int h = tid; h < 180; h += 256) {
        const float2* xp = xn2 + h * 25;
        float s0 = 0.0f, s1 = 0.0f;
        #pragma unroll
        for (int t = 0; t < 25; ++t) {
            float2 v = xp[t];
            s0 += v.x; s1 += v.y;
        }
        A[h + 1] = (s0 + s1) / 50.0f;
    }
    __syncthreads();

    // ---- stage 1: conv (16,1,3) pad 1 + rate -> r1 (all 16 channels) ----
    for (int idx = tid; idx < 16 * 180; idx += 256) {
        int o = idx / 180, h = idx - o * 180;
        float a = b1[o]
                + A[h]     * w1[o * 3]
                + A[h + 1] * w1[o * 3 + 1]
                + A[h + 2] * w1[o * 3 + 2];
        B[o * 184 + h + 1] = rate50(a);
    }
    __syncthreads();

    // ---- stage 2: conv (32,16,9) pad 1 + rate for o in [obase, obase+16) ----
    // 16 threads per output channel, h-chunk of 11 (176 slots, 174 valid).
    // Window LDS: 16 distinct banks ({11s} mod 32), upper half-warp broadcasts.
    {
        int ol = tid >> 4;
        int h0 = (tid & 15) * 11;
        float acc[11];
        float bb = b2[obase + ol];
        #pragma unroll
        for (int j = 0; j < 11; ++j) acc[j] = bb;
        const float* wrow = W2s + ol * 145;
        #pragma unroll 1
        for (int c = 0; c < 16; ++c) {
            float win[19];
            const float* row = B + c * 184 + h0;
            #pragma unroll
            for (int j = 0; j < 19; ++j) win[j] = row[j];
            const float* wp = wrow + c * 9;
            #pragma unroll
            for (int k = 0; k < 9; ++k) {
                float wv = wp[k];
                #pragma unroll
                for (int j = 0; j < 11; ++j) acc[j] += win[j + k] * wv;
            }
        }
        #pragma unroll
        for (int j = 0; j < 11; ++j) C[ol * 176 + h0 + j] = rate50(acc[j]);  // 174 valid
    }
    __syncthreads();

    // ---- stage 3: sum-pool(2)*1.1 + rate -> g_r3[n][obase+ol][h] ----
    float* r3n = g_r3 + (long)n * (32 * 87) + obase * 87;
    for (int idx = tid; idx < 16 * 87; idx += 256) {
        int ol = idx / 87, h = idx - ol * 87;
        float a = 1.1f * (C[ol * 176 + 2 * h] + C[ol * 176 + 2 * h + 1]);
        r3n[ol * 87 + h] = rate50(a);
    }
}

// ===================== K2: half of r4, dense partial -> atomicAdd =====================
// Shared (floats): B r3 [0,3840) 32 x stride 120 (data at h+1, pads zero);
// C r4local [3840,5264) 16 x stride 89; W3s [5264,8864) 16 rows x stride 225;
// A scratch [8864,8896).
#define K2_C   3840
#define K2_W3  5264
#define K2_A   8864
#define K2_TOT 8896

__global__ __launch_bounds__(256, 4)
void catnet_k2(const float* __restrict__ w3, const float* __restrict__ b3,
               const float* __restrict__ wf, const float* __restrict__ bf,
               float* __restrict__ out) {
    __shared__ float sm[K2_TOT];
    float* B   = sm;
    float* C   = sm + K2_C;
    float* W3s = sm + K2_W3;
    float* A   = sm + K2_A;
    const int tid = threadIdx.x;
    const int n = blockIdx.x >> 1;
    const int cg = blockIdx.x & 1;
    const int obase = cg * 16;

    // stage this CTA's 16 w3 output rows (32*7 floats each) into smem
    #pragma unroll 2
    for (int i = tid; i < 16 * 224; i += 256) {
        int ol = i / 224;
        int r = i - ol * 224;
        W3s[ol * 225 + r] = w3[(obase + ol) * 224 + r];
    }
    // zero r3 region (pads + finite under over-reads)
    for (int i = tid; i < K2_C; i += 256) sm[i] = 0.0f;
    __syncthreads();

    // ---- load ALL 32 r3 channels -> B (stride 120, data at h+1) ----
    const float* r3n = g_r3 + (long)n * (32 * 87);
    for (int idx = tid; idx < 32 * 87; idx += 256) {
        int o = idx / 87, h = idx - o * 87;
        B[o * 120 + h + 1] = r3n[idx];
    }
    __syncthreads();

    // ---- stage 4: conv (32,32,7) pad 1 + rate for o in [obase, obase+16) ----
    // 16 threads per output channel, h-chunk of 6 (96 slots, 83 valid).
    // Window LDS: 16 distinct banks ({6s} mod 32), upper half-warp broadcasts.
    {
        int ol = tid >> 4;
        int h0 = (tid & 15) * 6;
        float acc[6];
        float bb = b3[obase + ol];
        #pragma unroll
        for (int j = 0; j < 6; ++j) acc[j] = bb;
        const float* wrow = W3s + ol * 225;
        #pragma unroll 1
        for (int c = 0; c < 32; ++c) {
            float win[12];
            const float* row = B + c * 120 + h0;
            #pragma unroll
            for (int j = 0; j < 12; ++j) win[j] = row[j];
            const float* wp = wrow + c * 7;
            #pragma unroll
            for (int k = 0; k < 7; ++k) {
                float wv = wp[k];
                #pragma unroll
                for (int j = 0; j < 6; ++j) acc[j] += win[j + k] * wv;
            }
        }
        #pragma unroll
        for (int j = 0; j < 6; ++j) {
            int h = h0 + j;
            if (h < 83) C[ol * 89 + h] = rate50(acc[j]);
        }
    }
    __syncthreads();

    // ---- stage 5: dense partial over this CTA's 16 r4 channels ----
    {
        float p0 = 0.f, p1 = 0.f, p2 = 0.f, p3 = 0.f;
        for (int idx = tid; idx < 16 * 83; idx += 256) {
            int cl = idx / 83, h = idx - cl * 83;
            float v = C[cl * 89 + h];
            int wi = (obase + cl) * 83 + h;
            p0 += v * wf[wi];
            p1 += v * wf[wi + 2656];
            p2 += v * wf[wi + 2 * 2656];
            p3 += v * wf[wi + 3 * 2656];
        }
        #pragma unroll
        for (int off = 16; off; off >>= 1) {
            p0 += __shfl_down_sync(0xffffffffu, p0, off);
            p1 += __shfl_down_sync(0xffffffffu, p1, off);
            p2 += __shfl_down_sync(0xffffffffu, p2, off);
            p3 += __shfl_down_sync(0xffffffffu, p3, off);
        }
        int lane = tid & 31, wid = tid >> 5;
        if (lane == 0) {
            A[wid * 4 + 0] = p0;
            A[wid * 4 + 1] = p1;
            A[wid * 4 + 2] = p2;
            A[wid * 4 + 3] = p3;
        }
    }
    __syncthreads();
    if (tid < 4) {
        float s = (cg == 0) ? bf[tid] : 0.0f;   // bias added exactly once
        #pragma unroll
        for (int w = 0; w < 8; ++w) s += A[w * 4 + tid];
        atomicAdd(&out[n * 4 + tid], s);        // 2 commutative adds -> deterministic
    }
}

extern "C" void kernel_launch(void* const* d_in, const int* in_sizes, int n_in,
                              void* d_out, int out_size) {
    const float* x  = (const float*)d_in[0];
    const float* w1 = (const float*)d_in[1];
    const float* b1 = (const float*)d_in[2];
    const float* w2 = (const float*)d_in[3];
    const float* b2 = (const float*)d_in[4];
    const float* w3 = (const float*)d_in[5];
    const float* b3 = (const float*)d_in[6];
    const float* wf = (const float*)d_in[7];
    const float* bf = (const float*)d_in[8];
    float* out = (float*)d_out;

    int n = in_sizes[0] / (180 * 50);   // batch size (256)
    zero_out_kernel<<<(out_size + 255) / 256, 256>>>(out, out_size);
    catnet_k1<<<2 * n, 256>>>(x, w1, b1, w2, b2);
    catnet_k2<<<2 * n, 256>>>(w3, b3, wf, bf, out);
}

// round 17
// speedup vs baseline: 1.2225x; 1.2225x over previous
#include <cuda_runtime.h>

#define THETA 0.9999f

// IF-neuron spike rate over 50 steps, constant drive a, soft reset.
// Closed form floor(50*a/theta); exact f32 sim only near count boundaries.
__device__ __forceinline__ float rate50(float a) {
    if (a <= 0.0f) return 0.0f;
    if (a >= THETA) return 1.0f;
    float u = a * (50.0f / THETA);
    float k = floorf(u);
    float d = u - k;
    if (d > 1e-4f && d < 0.9999f) {
        return k * 0.02f;
    }
    float v = 0.0f, cnt = 0.0f;
    #pragma unroll
    for (int t = 0; t < 50; ++t) {
        v += a;
        if (v >= THETA) { v -= THETA; cnt += 1.0f; }
    }
    return cnt * 0.02f;
}

// Dynamic shared layout (floats):
//   A  [0,184)        : mx (data at h+1, pads zero); later warp-reduction partials (64)
//   B  [184,4056)     : r1 (16 x stride 208, data at h+1) then r3 (32 x stride 121, data at h+1)
//   C  [4056,9688)    : r2 (32 x stride 176) then r4 (32 x stride 89)
//   W2 [9688,14328)   : w2 staged, 32 rows stride 145 (o*145 + c*9 + k)
//   W3 [14328,21528)  : w3 staged, 32 rows stride 225 (o*225 + c*7 + k)
// Bank design (warp = 2 adjacent o x 16 h-chunks):
//   stage2 window: {11s mod 32} U {11s+16} = all 32 banks -> r1 stride 208 (=16 mod 32)
//   stage4 window: {6s mod 32}=evens U {6s+25}=odds      -> r3 stride 121 (=25 mod 32)
#define B_OFF   184
#define C_OFF   4056
#define W2_OFF  9688
#define W3_OFF  14328
#define SM_TOTAL 21528
#define SMEM_BYTES (SM_TOTAL * 4)

__global__ __launch_bounds__(512, 2)
void catnet_kernel(const float* __restrict__ x,
                   const float* __restrict__ w1, const float* __restrict__ b1,
                   const float* __restrict__ w2, const float* __restrict__ b2,
                   const float* __restrict__ w3, const float* __restrict__ b3,
                   const float* __restrict__ wf, const float* __restrict__ bf,
                   float* __restrict__ out) {
    extern __shared__ float sm[];
    float* A   = sm;
    float* B   = sm + B_OFF;
    float* C   = sm + C_OFF;
    float* W2s = sm + W2_OFF;
    float* W3s = sm + W3_OFF;
    const int tid = threadIdx.x;
    const int n = blockIdx.x;

    // Stage weights global->shared (issued first; latency overlapped with
    // stages 0-1, complete by the pre-stage-2 barrier).
    #pragma unroll 2
    for (int i = tid; i < 32 * 144; i += 512) {
        int o = i / 144;
        W2s[o * 145 + (i - o * 144)] = w2[i];
    }
    #pragma unroll 2
    for (int i = tid; i < 32 * 224; i += 512) {
        int o = i / 224;
        W3s[o * 225 + (i - o * 224)] = w3[i];
    }

    // zero working region (pad cells + finite values for chunk-tail over-reads)
    for (int i = tid; i < W2_OFF; i += 512) sm[i] = 0.0f;
    __syncthreads();

    // ---- stage 0: mean over time: x[n,0,h,0,t] -> A[h+1] ----
    const float2* xn2 = (const float2*)(x + (long)n * (180 * 50));
    if (tid < 180) {
        const float2* xp = xn2 + tid * 25;
        float s0 = 0.0f, s1 = 0.0f;
        #pragma unroll
        for (int t = 0; t < 25; ++t) {
            float2 v = xp[t];
            s0 += v.x; s1 += v.y;
        }
        A[tid + 1] = (s0 + s1) / 50.0f;
    }
    __syncthreads();

    // ---- stage 1: conv (16,1,3) pad 1 + rate -> B (r1, stride 208, data at h+1) ----
    for (int idx = tid; idx < 16 * 180; idx += 512) {
        int o = idx / 180, h = idx - o * 180;
        float a = b1[o]
                + A[h]     * w1[o * 3]
                + A[h + 1] * w1[o * 3 + 1]
                + A[h + 2] * w1[o * 3 + 2];
        B[o * 208 + h + 1] = rate50(a);
    }
    __syncthreads();   // also guarantees weight staging is complete

    // ---- stage 2: conv (32,16,9) pad 1 + rate -> C (r2, stride 176) ----
    // thread -> (o = tid/16, h-chunk of 11). Warp covers 2 o x 16 chunks;
    // window LDS conflict-free by the d=16 stride design.
    {
        int o = tid >> 4;
        int h0 = (tid & 15) * 11;
        float acc[11];
        float bb = b2[o];
        #pragma unroll
        for (int j = 0; j < 11; ++j) acc[j] = bb;
        const float* wrow = W2s + o * 145;
        #pragma unroll 1
        for (int c = 0; c < 16; ++c) {
            float win[19];
            const float* row = B + c * 208 + h0;
            #pragma unroll
            for (int j = 0; j < 19; ++j) win[j] = row[j];
            const float* wp = wrow + c * 9;
            #pragma unroll
            for (int k = 0; k < 9; ++k) {
                float wv = wp[k];
                #pragma unroll
                for (int j = 0; j < 11; ++j) acc[j] += win[j + k] * wv;
            }
        }
        #pragma unroll
        for (int j = 0; j < 11; ++j) {
            int h = h0 + j;
            if (h < 174) C[o * 176 + h] = rate50(acc[j]);
        }
    }
    __syncthreads();

    // ---- stage 3: sum-pool(2)*1.1 + rate -> B (r3, stride 121, data at h+1) ----
    for (int idx = tid; idx < 32 * 87; idx += 512) {
        int o = idx / 87, h = idx - o * 87;
        float a = 1.1f * (C[o * 176 + 2 * h] + C[o * 176 + 2 * h + 1]);
        B[o * 121 + h + 1] = rate50(a);
    }
    // zero r3 pad cells (region previously held r1 data): index 0 and [88,121)
    // per row — disjoint from the writes above, so same phase is race-free.
    // Also zero reduction scratch (mx dead).
    if (tid < 32) {
        B[tid * 121] = 0.0f;
        #pragma unroll
        for (int j = 88; j < 121; ++j) B[tid * 121 + j] = 0.0f;
        A[tid] = 0.0f;
        A[32 + tid] = 0.0f;
    }
    __syncthreads();

    // ---- stage 4: conv (32,32,7) pad 1 + rate -> C (r4, stride 89) ----
    // thread -> (o = tid/16, h-chunk of 6). Window LDS conflict-free
    // (evens from o-even lanes, odds from o-odd lanes).
    {
        int o = tid >> 4;
        int h0 = (tid & 15) * 6;
        float acc[6];
        float bb = b3[o];
        #pragma unroll
        for (int j = 0; j < 6; ++j) acc[j] = bb;
        const float* wrow = W3s + o * 225;
        #pragma unroll 1
        for (int c = 0; c < 32; ++c) {
            float win[12];
            const float* row = B + c * 121 + h0;
            #pragma unroll
            for (int j = 0; j < 12; ++j) win[j] = row[j];
            const float* wp = wrow + c * 7;
            #pragma unroll
            for (int k = 0; k < 7; ++k) {
                float wv = wp[k];
                #pragma unroll
                for (int j = 0; j < 6; ++j) acc[j] += win[j + k] * wv;
            }
        }
        #pragma unroll
        for (int j = 0; j < 6; ++j) {
            int h = h0 + j;
            if (h < 83) C[o * 89 + h] = rate50(acc[j]);
        }
    }
    __syncthreads();

    // ---- stage 5: dense out[n,o] = sum_{c,h} r4[c,h]*wf[o,c,h] + bf[o] ----
    {
        float p0 = 0.f, p1 = 0.f, p2 = 0.f, p3 = 0.f;
        for (int idx = tid; idx < 32 * 83; idx += 512) {
            int c = idx / 83, h = idx - c * 83;
            float v = C[c * 89 + h];
            int wi = c * 83 + h;
            p0 += v * wf[wi];
            p1 += v * wf[wi + 2656];
            p2 += v * wf[wi + 2 * 2656];
            p3 += v * wf[wi + 3 * 2656];
        }
        #pragma unroll
        for (int off = 16; off; off >>= 1) {
            p0 += __shfl_down_sync(0xffffffffu, p0, off);
            p1 += __shfl_down_sync(0xffffffffu, p1, off);
            p2 += __shfl_down_sync(0xffffffffu, p2, off);
            p3 += __shfl_down_sync(0xffffffffu, p3, off);
        }
        int lane = tid & 31, wid = tid >> 5;
        if (lane == 0) {
            A[wid * 4 + 0] = p0;
            A[wid * 4 + 1] = p1;
            A[wid * 4 + 2] = p2;
            A[wid * 4 + 3] = p3;
        }
    }
    __syncthreads();
    if (tid < 4) {
        float s = bf[tid];
        #pragma unroll
        for (int w = 0; w < 16; ++w) s += A[w * 4 + tid];
        out[n * 4 + tid] = s;
    }
}

extern "C" void kernel_launch(void* const* d_in, const int* in_sizes, int n_in,
                              void* d_out, int out_size) {
    const float* x  = (const float*)d_in[0];
    const float* w1 = (const float*)d_in[1];
    const float* b1 = (const float*)d_in[2];
    const float* w2 = (const float*)d_in[3];
    const float* b2 = (const float*)d_in[4];
    const float* w3 = (const float*)d_in[5];
    const float* b3 = (const float*)d_in[6];
    const float* wf = (const float*)d_in[7];
    const float* bf = (const float*)d_in[8];
    float* out = (float*)d_out;

    cudaFuncSetAttribute(catnet_kernel,
                         cudaFuncAttributeMaxDynamicSharedMemorySize, SMEM_BYTES);

    int n = in_sizes[0] / (180 * 50);   // batch size (256)
    catnet_kernel<<<n, 512, SMEM_BYTES>>>(x, w1, b1, w2, b2, w3, b3, wf, bf, out);
}